// round 1
// baseline (speedup 1.0000x reference)
#include <cuda_runtime.h>
#include <math.h>

#define Nn 16384
#define Dd 512
#define Kk 1024
#define NUM_ITERS 10
#define TEMPERATURE 0.1f
#define CONCENTRATION 0.1f
#define EPSf 1e-6f

#define NCHUNK 64          // N / 256 chunks for stable scatter
#define CHUNK  256

// ---------------- device scratch (static, no runtime alloc) ----------------
__device__ float  g_cent[Kk * Dd];      // centroids (2 MB)
__device__ float  g_xsq[Nn];
__device__ float  g_csq[Kk];
__device__ int    g_asg[Nn];
__device__ int    g_counts[Kk];
__device__ int    g_offsets[Kk];
__device__ int    g_hist[NCHUNK * Kk];  // per-chunk per-cluster base positions
__device__ int    g_order[Nn];
__device__ float  g_dists[Kk * Dd];     // per (cluster, dim) residual sums (2 MB)
__device__ double g_part1[256];
__device__ double g_part2a[256];
__device__ double g_part2b[256];
__device__ double g_S;

// ---------------- init: centroids = feats[:K] ----------------
__global__ void copy_init_kernel(const float* __restrict__ feats) {
    int i = blockIdx.x * blockDim.x + threadIdx.x;
    if (i < Kk * Dd) g_cent[i] = feats[i];
}

// ---------------- row squared norms (warp per row) ----------------
__global__ void xsq_kernel(const float* __restrict__ x) {
    int warp = (blockIdx.x * blockDim.x + threadIdx.x) >> 5;
    int lane = threadIdx.x & 31;
    if (warp >= Nn) return;
    const float4* r = (const float4*)(x + (size_t)warp * Dd);
    float s = 0.f;
#pragma unroll
    for (int i = 0; i < Dd / 128; i++) {
        float4 v = r[lane + i * 32];
        s += v.x * v.x + v.y * v.y + v.z * v.z + v.w * v.w;
    }
#pragma unroll
    for (int o = 16; o; o >>= 1) s += __shfl_xor_sync(0xffffffffu, s, o);
    if (lane == 0) g_xsq[warp] = s;
}

__global__ void csq_kernel() {
    int warp = (blockIdx.x * blockDim.x + threadIdx.x) >> 5;
    int lane = threadIdx.x & 31;
    if (warp >= Kk) return;
    const float4* r = (const float4*)(g_cent + (size_t)warp * Dd);
    float s = 0.f;
#pragma unroll
    for (int i = 0; i < Dd / 128; i++) {
        float4 v = r[lane + i * 32];
        s += v.x * v.x + v.y * v.y + v.z * v.z + v.w * v.w;
    }
#pragma unroll
    for (int o = 16; o; o >>= 1) s += __shfl_xor_sync(0xffffffffu, s, o);
    if (lane == 0) g_csq[warp] = s;
}

// ---------------- assignment: tiled GEMM + argmin ----------------
// BM=64 points/block, BN=64 clusters per chunk, BK=32 d-slice,
// 128 threads, 8x4 register micro-tile.
#define BM 64
#define BN 64
#define BKC 32

__global__ __launch_bounds__(128) void assign_kernel(const float* __restrict__ feats) {
    __shared__ __align__(16) float As[BKC][BM + 4];
    __shared__ __align__(16) float Bs[BKC][BN + 4];
    __shared__ float rd[BM][17];
    __shared__ int   ri[BM][17];

    int tid = threadIdx.x;
    int mg  = tid >> 4;    // 0..7  -> points mg*8 .. mg*8+7
    int tn  = tid & 15;    // 0..15 -> clusters tn*4 .. tn*4+3 (within chunk)
    int row0 = blockIdx.x * BM;
    int r0 = tid >> 3;     // 0..15 loader row group
    int q  = tid & 7;      // 0..7  loader float4 column

    float best[8];
    int   bidx[8];
    float xs[8];
#pragma unroll
    for (int i = 0; i < 8; i++) {
        best[i] = 3.4e38f;
        bidx[i] = 0;
        xs[i] = g_xsq[row0 + mg * 8 + i];
    }

    for (int ck = 0; ck < Kk; ck += BN) {
        float acc[8][4];
#pragma unroll
        for (int i = 0; i < 8; i++)
#pragma unroll
            for (int j = 0; j < 4; j++) acc[i][j] = 0.f;

        for (int d0 = 0; d0 < Dd; d0 += BKC) {
            __syncthreads();
#pragma unroll
            for (int j = 0; j < 4; j++) {
                int r = r0 + 16 * j;
                float4 v = *(const float4*)(feats + (size_t)(row0 + r) * Dd + d0 + q * 4);
                As[q * 4 + 0][r] = v.x; As[q * 4 + 1][r] = v.y;
                As[q * 4 + 2][r] = v.z; As[q * 4 + 3][r] = v.w;
                float4 w = *(const float4*)(g_cent + (size_t)(ck + r) * Dd + d0 + q * 4);
                Bs[q * 4 + 0][r] = w.x; Bs[q * 4 + 1][r] = w.y;
                Bs[q * 4 + 2][r] = w.z; Bs[q * 4 + 3][r] = w.w;
            }
            __syncthreads();
#pragma unroll
            for (int d = 0; d < BKC; d++) {
                float4 a0 = *(const float4*)&As[d][mg * 8];
                float4 a1 = *(const float4*)&As[d][mg * 8 + 4];
                float4 b4 = *(const float4*)&Bs[d][tn * 4];
                float a[8] = {a0.x, a0.y, a0.z, a0.w, a1.x, a1.y, a1.z, a1.w};
                float b[4] = {b4.x, b4.y, b4.z, b4.w};
#pragma unroll
                for (int i = 0; i < 8; i++)
#pragma unroll
                    for (int j = 0; j < 4; j++)
                        acc[i][j] = fmaf(a[i], b[j], acc[i][j]);
            }
        }

#pragma unroll
        for (int i = 0; i < 8; i++) {
#pragma unroll
            for (int j = 0; j < 4; j++) {
                int c = ck + tn * 4 + j;
                float dd = xs[i] - 2.0f * acc[i][j] + g_csq[c];
                if (dd < best[i]) { best[i] = dd; bidx[i] = c; }
            }
        }
    }

#pragma unroll
    for (int i = 0; i < 8; i++) {
        rd[mg * 8 + i][tn] = best[i];
        ri[mg * 8 + i][tn] = bidx[i];
    }
    __syncthreads();
    if (tid < BM) {
        float bd = rd[tid][0];
        int   bi = ri[tid][0];
#pragma unroll
        for (int t = 1; t < 16; t++) {
            float dd = rd[tid][t];
            int   ii = ri[tid][t];
            if (dd < bd || (dd == bd && ii < bi)) { bd = dd; bi = ii; }
        }
        g_asg[row0 + tid] = bi;
    }
}

// ---------------- deterministic stable counting sort ----------------
// Phase 1: per-chunk histogram (smem atomics -> deterministic counts)
__global__ void histo_kernel() {
    __shared__ int h[Kk];
    int c = blockIdx.x;          // chunk index, 64 chunks of 256 points
    int t = threadIdx.x;         // 256 threads
#pragma unroll
    for (int i = t; i < Kk; i += CHUNK) h[i] = 0;
    __syncthreads();
    int k = g_asg[c * CHUNK + t];
    atomicAdd(&h[k], 1);
    __syncthreads();
#pragma unroll
    for (int i = t; i < Kk; i += CHUNK) g_hist[c * Kk + i] = h[i];
}

// Phase 2: single-block scan: counts, exclusive offsets, per-chunk absolute bases
__global__ void scan_kernel() {
    __shared__ int s[Kk];
    int t = threadIdx.x;  // 1024 threads = one per cluster
    int total = 0;
    for (int c = 0; c < NCHUNK; c++) total += g_hist[c * Kk + t];
    g_counts[t] = total;
    s[t] = total;
    __syncthreads();
    for (int o = 1; o < Kk; o <<= 1) {
        int v = (t >= o) ? s[t - o] : 0;
        __syncthreads();
        s[t] += v;
        __syncthreads();
    }
    int excl = (t == 0) ? 0 : s[t - 1];
    g_offsets[t] = excl;
    // rewrite hist in place: absolute base position for (chunk, cluster)
    int run = excl;
    for (int c = 0; c < NCHUNK; c++) {
        int h = g_hist[c * Kk + t];
        g_hist[c * Kk + t] = run;
        run += h;
    }
}

// Phase 3: stable scatter, rank within chunk computed without atomics
__global__ void scatter_kernel() {
    __shared__ int ka[CHUNK];
    int c = blockIdx.x;
    int t = threadIdx.x;
    int i = c * CHUNK + t;
    int k = g_asg[i];
    ka[t] = k;
    __syncthreads();
    int rank = 0;
    for (int j = 0; j < t; j++) rank += (ka[j] == k);
    g_order[g_hist[c * Kk + k] + rank] = i;
}

// ---------------- centroid update ----------------
__global__ void update_kernel(const float* __restrict__ feats) {
    int k = blockIdx.x;
    int cnt = g_counts[k];
    if (cnt == 0) return;  // keep old centroid
    int start = g_offsets[k];
    float inv = 1.0f / (float)cnt;
    for (int d = threadIdx.x; d < Dd; d += blockDim.x) {
        float s = 0.f;
        for (int j = 0; j < cnt; j++)
            s += feats[(size_t)g_order[start + j] * Dd + d];
        g_cent[(size_t)k * Dd + d] = s * (float)cnt * inv * inv; // == s / cnt
    }
}

// ---------------- per-(cluster,dim) residual sums ----------------
__global__ void dists_kernel(const float* __restrict__ feats) {
    int k = blockIdx.x;
    int cnt = g_counts[k];
    int start = g_offsets[k];
    for (int d = threadIdx.x; d < Dd; d += blockDim.x) {
        float c = g_cent[(size_t)k * Dd + d];
        float s = 0.f;
        for (int j = 0; j < cnt; j++) {
            float r = feats[(size_t)g_order[start + j] * Dd + d] - c;
            s = fmaf(r, r, s);
        }
        g_dists[(size_t)k * Dd + d] = s;  // empty cluster -> 0 (matches segment_sum)
    }
}

// ---------------- final reductions ----------------
__global__ void reduce1_kernel() {
    double s = 0.0;
    int stride = gridDim.x * blockDim.x;
    for (int i = blockIdx.x * blockDim.x + threadIdx.x; i < Kk * Dd; i += stride)
        s += (double)expf(-g_dists[i] / CONCENTRATION);
    __shared__ double sm[256];
    sm[threadIdx.x] = s;
    __syncthreads();
    for (int o = 128; o; o >>= 1) {
        if (threadIdx.x < o) sm[threadIdx.x] += sm[threadIdx.x + o];
        __syncthreads();
    }
    if (threadIdx.x == 0) g_part1[blockIdx.x] = sm[0];
}

__global__ void finalize1_kernel() {
    __shared__ double sm[256];
    sm[threadIdx.x] = g_part1[threadIdx.x];
    __syncthreads();
    for (int o = 128; o; o >>= 1) {
        if (threadIdx.x < o) sm[threadIdx.x] += sm[threadIdx.x + o];
        __syncthreads();
    }
    if (threadIdx.x == 0) g_S = sm[0];
}

__global__ void reduce2_kernel() {
    float Sf = (float)g_S;
    double e1 = 0.0, e2 = 0.0;
    int stride = gridDim.x * blockDim.x;
    for (int i = blockIdx.x * blockDim.x + threadIdx.x; i < Kk * Dd; i += stride) {
        float dv = g_dists[i];
        float p  = expf(-dv / CONCENTRATION);
        float q  = p / Sf;
        e1 += (double)(q * logf(q + EPSf));
        float p2 = expf(-dv / TEMPERATURE);
        e2 += (double)logf(p2 + EPSf);
    }
    __shared__ double sa[256], sb[256];
    sa[threadIdx.x] = e1;
    sb[threadIdx.x] = e2;
    __syncthreads();
    for (int o = 128; o; o >>= 1) {
        if (threadIdx.x < o) {
            sa[threadIdx.x] += sa[threadIdx.x + o];
            sb[threadIdx.x] += sb[threadIdx.x + o];
        }
        __syncthreads();
    }
    if (threadIdx.x == 0) {
        g_part2a[blockIdx.x] = sa[0];
        g_part2b[blockIdx.x] = sb[0];
    }
}

__global__ void finalize2_kernel(float* __restrict__ out) {
    __shared__ double sa[256], sb[256];
    sa[threadIdx.x] = g_part2a[threadIdx.x];
    sb[threadIdx.x] = g_part2b[threadIdx.x];
    __syncthreads();
    for (int o = 128; o; o >>= 1) {
        if (threadIdx.x < o) {
            sa[threadIdx.x] += sa[threadIdx.x + o];
            sb[threadIdx.x] += sb[threadIdx.x + o];
        }
        __syncthreads();
    }
    if (threadIdx.x == 0) {
        double kd = (double)(Kk * Dd);
        double entropy = (sa[0] / kd);          // / NUM_CLUSTER_ITERS (=1)
        double nll = -(sb[0] / kd);
        out[0] = (float)(entropy + nll);
    }
}

// ---------------- launch ----------------
extern "C" void kernel_launch(void* const* d_in, const int* in_sizes, int n_in,
                              void* d_out, int out_size) {
    const float* feats = (const float*)d_in[0];
    float* out = (float*)d_out;
    (void)in_sizes; (void)n_in; (void)out_size;

    copy_init_kernel<<<(Kk * Dd + 255) / 256, 256>>>(feats);
    xsq_kernel<<<(Nn * 32) / 256, 256>>>(feats);

    for (int it = 0; it < NUM_ITERS; it++) {
        csq_kernel<<<(Kk * 32) / 256, 256>>>();
        assign_kernel<<<Nn / BM, 128>>>(feats);
        histo_kernel<<<NCHUNK, CHUNK>>>();
        scan_kernel<<<1, Kk>>>();
        scatter_kernel<<<NCHUNK, CHUNK>>>();
        update_kernel<<<Kk, 128>>>(feats);
    }

    // final assignment + statistics
    csq_kernel<<<(Kk * 32) / 256, 256>>>();
    assign_kernel<<<Nn / BM, 128>>>(feats);
    histo_kernel<<<NCHUNK, CHUNK>>>();
    scan_kernel<<<1, Kk>>>();
    scatter_kernel<<<NCHUNK, CHUNK>>>();
    dists_kernel<<<Kk, 128>>>(feats);

    reduce1_kernel<<<256, 256>>>();
    finalize1_kernel<<<1, 256>>>();
    reduce2_kernel<<<256, 256>>>();
    finalize2_kernel<<<1, 256>>>(out);
}

// round 2
// speedup vs baseline: 1.1139x; 1.1139x over previous
#include <cuda_runtime.h>
#include <math.h>

#define Nn 16384
#define Dd 512
#define Kk 1024
#define NUM_ITERS 10
#define TEMPERATURE 0.1f
#define CONCENTRATION 0.1f
#define EPSf 1e-6f

#define NCHUNK 64
#define CHUNK  256

// ---------------- device scratch ----------------
__device__ float  g_cent[Kk * Dd];
__device__ float  g_xsq[Nn];
__device__ float  g_csq[Kk];
__device__ int    g_asg[Nn];
__device__ int    g_counts[Kk];
__device__ int    g_offsets[Kk];
__device__ int    g_hist[NCHUNK * Kk];
__device__ int    g_order[Nn];
__device__ float  g_dists[Kk * Dd];
__device__ double g_part1[256];
__device__ double g_part2a[256];
__device__ double g_part2b[256];
__device__ double g_S;

__global__ void copy_init_kernel(const float* __restrict__ feats) {
    int i = blockIdx.x * blockDim.x + threadIdx.x;
    if (i < Kk * Dd) g_cent[i] = feats[i];
}

__global__ void xsq_kernel(const float* __restrict__ x) {
    int warp = (blockIdx.x * blockDim.x + threadIdx.x) >> 5;
    int lane = threadIdx.x & 31;
    if (warp >= Nn) return;
    const float4* r = (const float4*)(x + (size_t)warp * Dd);
    float s = 0.f;
#pragma unroll
    for (int i = 0; i < Dd / 128; i++) {
        float4 v = r[lane + i * 32];
        s += v.x * v.x + v.y * v.y + v.z * v.z + v.w * v.w;
    }
#pragma unroll
    for (int o = 16; o; o >>= 1) s += __shfl_xor_sync(0xffffffffu, s, o);
    if (lane == 0) g_xsq[warp] = s;
}

__global__ void csq_kernel() {
    int warp = (blockIdx.x * blockDim.x + threadIdx.x) >> 5;
    int lane = threadIdx.x & 31;
    if (warp >= Kk) return;
    const float4* r = (const float4*)(g_cent + (size_t)warp * Dd);
    float s = 0.f;
#pragma unroll
    for (int i = 0; i < Dd / 128; i++) {
        float4 v = r[lane + i * 32];
        s += v.x * v.x + v.y * v.y + v.z * v.z + v.w * v.w;
    }
#pragma unroll
    for (int o = 16; o; o >>= 1) s += __shfl_xor_sync(0xffffffffu, s, o);
    if (lane == 0) g_csq[warp] = s;
}

// ---------------- assignment: tiled GEMM + argmin ----------------
// BM=64 rows, BN=128 clusters per chunk (8 chunks), BK=16, 128 threads,
// 8x8 micro-tile, double-buffered smem (1 sync per K-slice).
#define BM 64
#define BN 128
#define BKC 16
#define NIT ((Kk / BN) * (Dd / BKC))   // 8 * 32 = 256

#define LOAD_TILE(it_, buf_)                                                      \
    do {                                                                          \
        int ck_ = ((it_) >> 5) << 7;                                              \
        int d0_ = ((it_) & 31) << 4;                                              \
        _Pragma("unroll")                                                         \
        for (int u_ = 0; u_ < 2; u_++) {                                          \
            int idx_ = tid + u_ * 128;                                            \
            int row_ = idx_ >> 2, q_ = idx_ & 3;                                  \
            float4 v_ = *(const float4*)(feats + (size_t)(row0 + row_) * Dd +     \
                                         d0_ + q_ * 4);                           \
            As[buf_][q_ * 4 + 0][row_] = v_.x;                                    \
            As[buf_][q_ * 4 + 1][row_] = v_.y;                                    \
            As[buf_][q_ * 4 + 2][row_] = v_.z;                                    \
            As[buf_][q_ * 4 + 3][row_] = v_.w;                                    \
        }                                                                         \
        _Pragma("unroll")                                                         \
        for (int u_ = 0; u_ < 4; u_++) {                                          \
            int idx_ = tid + u_ * 128;                                            \
            int row_ = idx_ >> 2, q_ = idx_ & 3;                                  \
            float4 w_ = *(const float4*)(g_cent + (size_t)(ck_ + row_) * Dd +     \
                                         d0_ + q_ * 4);                           \
            Bs[buf_][q_ * 4 + 0][row_] = w_.x;                                    \
            Bs[buf_][q_ * 4 + 1][row_] = w_.y;                                    \
            Bs[buf_][q_ * 4 + 2][row_] = w_.z;                                    \
            Bs[buf_][q_ * 4 + 3][row_] = w_.w;                                    \
        }                                                                         \
    } while (0)

__global__ __launch_bounds__(128) void assign_kernel(const float* __restrict__ feats) {
    __shared__ __align__(16) float As[2][BKC][BM + 4];
    __shared__ __align__(16) float Bs[2][BKC][BN + 4];
    __shared__ float rd[BM][17];
    __shared__ int   ri[BM][17];

    int tid = threadIdx.x;
    int ty  = tid >> 4;   // 0..7  -> rows ty*8 .. +7
    int tx  = tid & 15;   // 0..15 -> cols tx*8 .. +7 (within chunk)
    int row0 = blockIdx.x * BM;

    float xs[8], best[8];
    int bidx[8];
#pragma unroll
    for (int i = 0; i < 8; i++) {
        xs[i] = g_xsq[row0 + ty * 8 + i];
        best[i] = 3.4e38f;
        bidx[i] = 0;
    }

    float acc[8][8];
#pragma unroll
    for (int i = 0; i < 8; i++)
#pragma unroll
        for (int j = 0; j < 8; j++) acc[i][j] = 0.f;

    LOAD_TILE(0, 0);
    __syncthreads();

    int buf = 0;
    for (int it = 0; it < NIT; it++) {
        if (it + 1 < NIT) LOAD_TILE(it + 1, buf ^ 1);

#pragma unroll
        for (int d = 0; d < BKC; d++) {
            float4 a0 = *(const float4*)&As[buf][d][ty * 8];
            float4 a1 = *(const float4*)&As[buf][d][ty * 8 + 4];
            float4 b0 = *(const float4*)&Bs[buf][d][tx * 8];
            float4 b1 = *(const float4*)&Bs[buf][d][tx * 8 + 4];
            float a[8] = {a0.x, a0.y, a0.z, a0.w, a1.x, a1.y, a1.z, a1.w};
            float b[8] = {b0.x, b0.y, b0.z, b0.w, b1.x, b1.y, b1.z, b1.w};
#pragma unroll
            for (int i = 0; i < 8; i++)
#pragma unroll
                for (int j = 0; j < 8; j++)
                    acc[i][j] = fmaf(a[i], b[j], acc[i][j]);
        }

        if ((it & 31) == 31) {
            int ck = (it >> 5) << 7;
#pragma unroll
            for (int j = 0; j < 8; j++) {
                int c = ck + tx * 8 + j;
                float cs = g_csq[c];
#pragma unroll
                for (int i = 0; i < 8; i++) {
                    float dd = xs[i] - 2.0f * acc[i][j] + cs;
                    if (dd < best[i]) { best[i] = dd; bidx[i] = c; }
                    acc[i][j] = 0.f;
                }
            }
        }
        __syncthreads();
        buf ^= 1;
    }

#pragma unroll
    for (int i = 0; i < 8; i++) {
        rd[ty * 8 + i][tx] = best[i];
        ri[ty * 8 + i][tx] = bidx[i];
    }
    __syncthreads();
    if (tid < BM) {
        float bd = rd[tid][0];
        int   bi = ri[tid][0];
#pragma unroll
        for (int t = 1; t < 16; t++) {
            float dd = rd[tid][t];
            int   ii = ri[tid][t];
            if (dd < bd || (dd == bd && ii < bi)) { bd = dd; bi = ii; }
        }
        g_asg[row0 + tid] = bi;
    }
}

// ---------------- deterministic stable counting sort ----------------
__global__ void histo_kernel() {
    __shared__ int h[Kk];
    int c = blockIdx.x;
    int t = threadIdx.x;
#pragma unroll
    for (int i = t; i < Kk; i += CHUNK) h[i] = 0;
    __syncthreads();
    int k = g_asg[c * CHUNK + t];
    atomicAdd(&h[k], 1);
    __syncthreads();
#pragma unroll
    for (int i = t; i < Kk; i += CHUNK) g_hist[c * Kk + i] = h[i];
}

__global__ void scan_kernel() {
    __shared__ int s[Kk];
    int t = threadIdx.x;
    int total = 0;
    for (int c = 0; c < NCHUNK; c++) total += g_hist[c * Kk + t];
    g_counts[t] = total;
    s[t] = total;
    __syncthreads();
    for (int o = 1; o < Kk; o <<= 1) {
        int v = (t >= o) ? s[t - o] : 0;
        __syncthreads();
        s[t] += v;
        __syncthreads();
    }
    int excl = (t == 0) ? 0 : s[t - 1];
    g_offsets[t] = excl;
    int run = excl;
    for (int c = 0; c < NCHUNK; c++) {
        int h = g_hist[c * Kk + t];
        g_hist[c * Kk + t] = run;
        run += h;
    }
}

__global__ void scatter_kernel() {
    __shared__ int ka[CHUNK];
    int c = blockIdx.x;
    int t = threadIdx.x;
    int i = c * CHUNK + t;
    int k = g_asg[i];
    ka[t] = k;
    __syncthreads();
    int rank = 0;
    for (int j = 0; j < t; j++) rank += (ka[j] == k);
    g_order[g_hist[c * Kk + k] + rank] = i;
}

__global__ void update_kernel(const float* __restrict__ feats) {
    int k = blockIdx.x;
    int cnt = g_counts[k];
    if (cnt == 0) return;
    int start = g_offsets[k];
    float inv = 1.0f / (float)cnt;
    for (int d = threadIdx.x; d < Dd; d += blockDim.x) {
        float s = 0.f;
        for (int j = 0; j < cnt; j++)
            s += feats[(size_t)g_order[start + j] * Dd + d];
        g_cent[(size_t)k * Dd + d] = s * (float)cnt * inv * inv;
    }
}

__global__ void dists_kernel(const float* __restrict__ feats) {
    int k = blockIdx.x;
    int cnt = g_counts[k];
    int start = g_offsets[k];
    for (int d = threadIdx.x; d < Dd; d += blockDim.x) {
        float c = g_cent[(size_t)k * Dd + d];
        float s = 0.f;
        for (int j = 0; j < cnt; j++) {
            float r = feats[(size_t)g_order[start + j] * Dd + d] - c;
            s = fmaf(r, r, s);
        }
        g_dists[(size_t)k * Dd + d] = s;
    }
}

__global__ void reduce1_kernel() {
    double s = 0.0;
    int stride = gridDim.x * blockDim.x;
    for (int i = blockIdx.x * blockDim.x + threadIdx.x; i < Kk * Dd; i += stride)
        s += (double)expf(-g_dists[i] / CONCENTRATION);
    __shared__ double sm[256];
    sm[threadIdx.x] = s;
    __syncthreads();
    for (int o = 128; o; o >>= 1) {
        if (threadIdx.x < o) sm[threadIdx.x] += sm[threadIdx.x + o];
        __syncthreads();
    }
    if (threadIdx.x == 0) g_part1[blockIdx.x] = sm[0];
}

__global__ void finalize1_kernel() {
    __shared__ double sm[256];
    sm[threadIdx.x] = g_part1[threadIdx.x];
    __syncthreads();
    for (int o = 128; o; o >>= 1) {
        if (threadIdx.x < o) sm[threadIdx.x] += sm[threadIdx.x + o];
        __syncthreads();
    }
    if (threadIdx.x == 0) g_S = sm[0];
}

__global__ void reduce2_kernel() {
    float Sf = (float)g_S;
    double e1 = 0.0, e2 = 0.0;
    int stride = gridDim.x * blockDim.x;
    for (int i = blockIdx.x * blockDim.x + threadIdx.x; i < Kk * Dd; i += stride) {
        float dv = g_dists[i];
        float p  = expf(-dv / CONCENTRATION);
        float q  = p / Sf;
        e1 += (double)(q * logf(q + EPSf));
        float p2 = expf(-dv / TEMPERATURE);
        e2 += (double)logf(p2 + EPSf);
    }
    __shared__ double sa[256], sb[256];
    sa[threadIdx.x] = e1;
    sb[threadIdx.x] = e2;
    __syncthreads();
    for (int o = 128; o; o >>= 1) {
        if (threadIdx.x < o) {
            sa[threadIdx.x] += sa[threadIdx.x + o];
            sb[threadIdx.x] += sb[threadIdx.x + o];
        }
        __syncthreads();
    }
    if (threadIdx.x == 0) {
        g_part2a[blockIdx.x] = sa[0];
        g_part2b[blockIdx.x] = sb[0];
    }
}

__global__ void finalize2_kernel(float* __restrict__ out) {
    __shared__ double sa[256], sb[256];
    sa[threadIdx.x] = g_part2a[threadIdx.x];
    sb[threadIdx.x] = g_part2b[threadIdx.x];
    __syncthreads();
    for (int o = 128; o; o >>= 1) {
        if (threadIdx.x < o) {
            sa[threadIdx.x] += sa[threadIdx.x + o];
            sb[threadIdx.x] += sb[threadIdx.x + o];
        }
        __syncthreads();
    }
    if (threadIdx.x == 0) {
        double kd = (double)(Kk * Dd);
        double entropy = (sa[0] / kd);
        double nll = -(sb[0] / kd);
        out[0] = (float)(entropy + nll);
    }
}

extern "C" void kernel_launch(void* const* d_in, const int* in_sizes, int n_in,
                              void* d_out, int out_size) {
    const float* feats = (const float*)d_in[0];
    float* out = (float*)d_out;
    (void)in_sizes; (void)n_in; (void)out_size;

    copy_init_kernel<<<(Kk * Dd + 255) / 256, 256>>>(feats);
    xsq_kernel<<<(Nn * 32) / 256, 256>>>(feats);

    for (int it = 0; it < NUM_ITERS; it++) {
        csq_kernel<<<(Kk * 32) / 256, 256>>>();
        assign_kernel<<<Nn / BM, 128>>>(feats);
        histo_kernel<<<NCHUNK, CHUNK>>>();
        scan_kernel<<<1, Kk>>>();
        scatter_kernel<<<NCHUNK, CHUNK>>>();
        update_kernel<<<Kk, 128>>>(feats);
    }

    csq_kernel<<<(Kk * 32) / 256, 256>>>();
    assign_kernel<<<Nn / BM, 128>>>(feats);
    histo_kernel<<<NCHUNK, CHUNK>>>();
    scan_kernel<<<1, Kk>>>();
    scatter_kernel<<<NCHUNK, CHUNK>>>();
    dists_kernel<<<Kk, 128>>>(feats);

    reduce1_kernel<<<256, 256>>>();
    finalize1_kernel<<<1, 256>>>();
    reduce2_kernel<<<256, 256>>>();
    finalize2_kernel<<<1, 256>>>(out);
}

// round 3
// speedup vs baseline: 1.2542x; 1.1259x over previous
#include <cuda_runtime.h>
#include <math.h>

#define Nn 16384
#define Dd 512
#define Kk 1024
#define NUM_ITERS 10
#define TEMPERATURE 0.1f
#define CONCENTRATION 0.1f
#define EPSf 1e-6f

#define NCHUNK 64
#define CHUNK  256

// ---------------- device scratch ----------------
__device__ float  g_cent[Kk * Dd];
__device__ float  g_xsq[Nn];
__device__ float  g_csq[Kk];
__device__ int    g_asg[Nn];
__device__ int    g_counts[Kk];
__device__ int    g_offsets[Kk];
__device__ int    g_hist[NCHUNK * Kk];
__device__ int    g_order[Nn];
__device__ float  g_dists[Kk * Dd];
__device__ double g_part1[256];
__device__ double g_part2a[256];
__device__ double g_part2b[256];
__device__ double g_S;

__global__ void copy_init_kernel(const float* __restrict__ feats) {
    int i = blockIdx.x * blockDim.x + threadIdx.x;
    if (i < Kk * Dd) g_cent[i] = feats[i];
}

__global__ void xsq_kernel(const float* __restrict__ x) {
    int warp = (blockIdx.x * blockDim.x + threadIdx.x) >> 5;
    int lane = threadIdx.x & 31;
    if (warp >= Nn) return;
    const float4* r = (const float4*)(x + (size_t)warp * Dd);
    float s = 0.f;
#pragma unroll
    for (int i = 0; i < Dd / 128; i++) {
        float4 v = r[lane + i * 32];
        s += v.x * v.x + v.y * v.y + v.z * v.z + v.w * v.w;
    }
#pragma unroll
    for (int o = 16; o; o >>= 1) s += __shfl_xor_sync(0xffffffffu, s, o);
    if (lane == 0) g_xsq[warp] = s;
}

__global__ void csq_kernel() {
    int warp = (blockIdx.x * blockDim.x + threadIdx.x) >> 5;
    int lane = threadIdx.x & 31;
    if (warp >= Kk) return;
    const float4* r = (const float4*)(g_cent + (size_t)warp * Dd);
    float s = 0.f;
#pragma unroll
    for (int i = 0; i < Dd / 128; i++) {
        float4 v = r[lane + i * 32];
        s += v.x * v.x + v.y * v.y + v.z * v.z + v.w * v.w;
    }
#pragma unroll
    for (int o = 16; o; o >>= 1) s += __shfl_xor_sync(0xffffffffu, s, o);
    if (lane == 0) g_csq[warp] = s;
}

// ---------------- assignment: tiled GEMM + argmin, FFMA2 ----------------
// BM=128 rows/block, BN=128 clusters per chunk (8 chunks), BK=16, 128 threads,
// 16x8 micro-tile as 8 row-pairs x 8 cols of packed f32x2 accumulators.
#define BM 128
#define BN 128
#define BKC 16
#define NIT ((Kk / BN) * (Dd / BKC))   // 8 * 32 = 256
#define APAD 4

#define LOAD_TILE(it_, buf_)                                                      \
    do {                                                                          \
        int ck_ = ((it_) >> 5) << 7;                                              \
        int d0_ = ((it_) & 31) << 4;                                              \
        _Pragma("unroll")                                                         \
        for (int u_ = 0; u_ < 4; u_++) {                                          \
            int idx_ = tid + u_ * 128;                                            \
            int row_ = idx_ >> 2, q_ = idx_ & 3;                                  \
            float4 v_ = *(const float4*)(feats + (size_t)(row0 + row_) * Dd +     \
                                         d0_ + q_ * 4);                           \
            As[buf_][q_ * 4 + 0][row_] = v_.x;                                    \
            As[buf_][q_ * 4 + 1][row_] = v_.y;                                    \
            As[buf_][q_ * 4 + 2][row_] = v_.z;                                    \
            As[buf_][q_ * 4 + 3][row_] = v_.w;                                    \
            float4 w_ = *(const float4*)(g_cent + (size_t)(ck_ + row_) * Dd +     \
                                         d0_ + q_ * 4);                           \
            Bs[buf_][q_ * 4 + 0][row_] = w_.x;                                    \
            Bs[buf_][q_ * 4 + 1][row_] = w_.y;                                    \
            Bs[buf_][q_ * 4 + 2][row_] = w_.z;                                    \
            Bs[buf_][q_ * 4 + 3][row_] = w_.w;                                    \
        }                                                                         \
    } while (0)

__global__ __launch_bounds__(128) void assign_kernel(const float* __restrict__ feats) {
    __shared__ __align__(16) float As[2][BKC][BM + APAD];
    __shared__ __align__(16) float Bs[2][BKC][BN + APAD];

    int tid = threadIdx.x;
    int ty  = tid >> 4;   // 0..7  -> rows ty*16 .. +15
    int tx  = tid & 15;   // 0..15 -> cols tx*8 .. +7 within chunk
    int row0 = blockIdx.x * BM;

    float xs[16], best[16];
    int bidx[16];
#pragma unroll
    for (int i = 0; i < 16; i++) {
        xs[i] = g_xsq[row0 + ty * 16 + i];
        best[i] = 3.4e38f;
        bidx[i] = 0;
    }

    // acc2[p][j]: packed f32x2 for rows (2p, 2p+1), column j
    unsigned long long acc2[8][8];
#pragma unroll
    for (int p = 0; p < 8; p++)
#pragma unroll
        for (int j = 0; j < 8; j++) acc2[p][j] = 0ull;

    LOAD_TILE(0, 0);
    __syncthreads();

    int buf = 0;
    for (int it = 0; it < NIT; it++) {
        if (it + 1 < NIT) LOAD_TILE(it + 1, buf ^ 1);

#pragma unroll
        for (int d = 0; d < BKC; d++) {
            // A row-pairs come directly as aligned u64 halves of 128-bit loads
            ulonglong2 a01 = *(const ulonglong2*)&As[buf][d][ty * 16];
            ulonglong2 a23 = *(const ulonglong2*)&As[buf][d][ty * 16 + 4];
            ulonglong2 a45 = *(const ulonglong2*)&As[buf][d][ty * 16 + 8];
            ulonglong2 a67 = *(const ulonglong2*)&As[buf][d][ty * 16 + 12];
            unsigned long long ap[8] = {a01.x, a01.y, a23.x, a23.y,
                                        a45.x, a45.y, a67.x, a67.y};
            float4 b0 = *(const float4*)&Bs[buf][d][tx * 8];
            float4 b1 = *(const float4*)&Bs[buf][d][tx * 8 + 4];
            float bv[8] = {b0.x, b0.y, b0.z, b0.w, b1.x, b1.y, b1.z, b1.w};
            unsigned long long bd2[8];
#pragma unroll
            for (int j = 0; j < 8; j++)
                asm("mov.b64 %0, {%1, %1};" : "=l"(bd2[j]) : "r"(__float_as_uint(bv[j])));
#pragma unroll
            for (int p = 0; p < 8; p++)
#pragma unroll
                for (int j = 0; j < 8; j++)
                    asm("fma.rn.f32x2 %0, %1, %2, %0;"
                        : "+l"(acc2[p][j]) : "l"(ap[p]), "l"(bd2[j]));
        }

        if ((it & 31) == 31) {
            int ck = (it >> 5) << 7;
#pragma unroll
            for (int j = 0; j < 8; j++) {
                int c = ck + tx * 8 + j;
                float cs = g_csq[c];
#pragma unroll
                for (int p = 0; p < 8; p++) {
                    unsigned int lo, hi;
                    asm("mov.b64 {%0, %1}, %2;" : "=r"(lo), "=r"(hi) : "l"(acc2[p][j]));
                    float d0v = xs[2 * p]     - 2.0f * __uint_as_float(lo) + cs;
                    float d1v = xs[2 * p + 1] - 2.0f * __uint_as_float(hi) + cs;
                    if (d0v < best[2 * p])     { best[2 * p]     = d0v; bidx[2 * p]     = c; }
                    if (d1v < best[2 * p + 1]) { best[2 * p + 1] = d1v; bidx[2 * p + 1] = c; }
                    acc2[p][j] = 0ull;
                }
            }
        }
        __syncthreads();
        buf ^= 1;
    }

    // argmin across the 16 column-threads of each row (consecutive lanes)
#pragma unroll
    for (int i = 0; i < 16; i++) {
        float bdv = best[i];
        int   biv = bidx[i];
#pragma unroll
        for (int o = 8; o; o >>= 1) {
            float od = __shfl_xor_sync(0xffffffffu, bdv, o);
            int   oi = __shfl_xor_sync(0xffffffffu, biv, o);
            if (od < bdv || (od == bdv && oi < biv)) { bdv = od; biv = oi; }
        }
        if (tx == 0) g_asg[row0 + ty * 16 + i] = biv;
    }
}

// ---------------- deterministic stable counting sort ----------------
__global__ void histo_kernel() {
    __shared__ int h[Kk];
    int c = blockIdx.x;
    int t = threadIdx.x;
#pragma unroll
    for (int i = t; i < Kk; i += CHUNK) h[i] = 0;
    __syncthreads();
    int k = g_asg[c * CHUNK + t];
    atomicAdd(&h[k], 1);
    __syncthreads();
#pragma unroll
    for (int i = t; i < Kk; i += CHUNK) g_hist[c * Kk + i] = h[i];
}

__global__ void scan_kernel() {
    __shared__ int s[Kk];
    int t = threadIdx.x;
    int total = 0;
    for (int c = 0; c < NCHUNK; c++) total += g_hist[c * Kk + t];
    g_counts[t] = total;
    s[t] = total;
    __syncthreads();
    for (int o = 1; o < Kk; o <<= 1) {
        int v = (t >= o) ? s[t - o] : 0;
        __syncthreads();
        s[t] += v;
        __syncthreads();
    }
    int excl = (t == 0) ? 0 : s[t - 1];
    g_offsets[t] = excl;
    int run = excl;
    for (int c = 0; c < NCHUNK; c++) {
        int h = g_hist[c * Kk + t];
        g_hist[c * Kk + t] = run;
        run += h;
    }
}

__global__ void scatter_kernel() {
    __shared__ int ka[CHUNK];
    int c = blockIdx.x;
    int t = threadIdx.x;
    int i = c * CHUNK + t;
    int k = g_asg[i];
    ka[t] = k;
    __syncthreads();
    int rank = 0;
    for (int j = 0; j < t; j++) rank += (ka[j] == k);
    g_order[g_hist[c * Kk + k] + rank] = i;
}

__global__ void update_kernel(const float* __restrict__ feats) {
    int k = blockIdx.x;
    int cnt = g_counts[k];
    if (cnt == 0) return;
    int start = g_offsets[k];
    float inv = 1.0f / (float)cnt;
    for (int d = threadIdx.x; d < Dd; d += blockDim.x) {
        float s = 0.f;
        for (int j = 0; j < cnt; j++)
            s += feats[(size_t)g_order[start + j] * Dd + d];
        g_cent[(size_t)k * Dd + d] = s * (float)cnt * inv * inv;
    }
}

__global__ void dists_kernel(const float* __restrict__ feats) {
    int k = blockIdx.x;
    int cnt = g_counts[k];
    int start = g_offsets[k];
    for (int d = threadIdx.x; d < Dd; d += blockDim.x) {
        float c = g_cent[(size_t)k * Dd + d];
        float s = 0.f;
        for (int j = 0; j < cnt; j++) {
            float r = feats[(size_t)g_order[start + j] * Dd + d] - c;
            s = fmaf(r, r, s);
        }
        g_dists[(size_t)k * Dd + d] = s;
    }
}

__global__ void reduce1_kernel() {
    double s = 0.0;
    int stride = gridDim.x * blockDim.x;
    for (int i = blockIdx.x * blockDim.x + threadIdx.x; i < Kk * Dd; i += stride)
        s += (double)expf(-g_dists[i] / CONCENTRATION);
    __shared__ double sm[256];
    sm[threadIdx.x] = s;
    __syncthreads();
    for (int o = 128; o; o >>= 1) {
        if (threadIdx.x < o) sm[threadIdx.x] += sm[threadIdx.x + o];
        __syncthreads();
    }
    if (threadIdx.x == 0) g_part1[blockIdx.x] = sm[0];
}

__global__ void finalize1_kernel() {
    __shared__ double sm[256];
    sm[threadIdx.x] = g_part1[threadIdx.x];
    __syncthreads();
    for (int o = 128; o; o >>= 1) {
        if (threadIdx.x < o) sm[threadIdx.x] += sm[threadIdx.x + o];
        __syncthreads();
    }
    if (threadIdx.x == 0) g_S = sm[0];
}

__global__ void reduce2_kernel() {
    float Sf = (float)g_S;
    double e1 = 0.0, e2 = 0.0;
    int stride = gridDim.x * blockDim.x;
    for (int i = blockIdx.x * blockDim.x + threadIdx.x; i < Kk * Dd; i += stride) {
        float dv = g_dists[i];
        float p  = expf(-dv / CONCENTRATION);
        float q  = p / Sf;
        e1 += (double)(q * logf(q + EPSf));
        float p2 = expf(-dv / TEMPERATURE);
        e2 += (double)logf(p2 + EPSf);
    }
    __shared__ double sa[256], sb[256];
    sa[threadIdx.x] = e1;
    sb[threadIdx.x] = e2;
    __syncthreads();
    for (int o = 128; o; o >>= 1) {
        if (threadIdx.x < o) {
            sa[threadIdx.x] += sa[threadIdx.x + o];
            sb[threadIdx.x] += sb[threadIdx.x + o];
        }
        __syncthreads();
    }
    if (threadIdx.x == 0) {
        g_part2a[blockIdx.x] = sa[0];
        g_part2b[blockIdx.x] = sb[0];
    }
}

__global__ void finalize2_kernel(float* __restrict__ out) {
    __shared__ double sa[256], sb[256];
    sa[threadIdx.x] = g_part2a[threadIdx.x];
    sb[threadIdx.x] = g_part2b[threadIdx.x];
    __syncthreads();
    for (int o = 128; o; o >>= 1) {
        if (threadIdx.x < o) {
            sa[threadIdx.x] += sa[threadIdx.x + o];
            sb[threadIdx.x] += sb[threadIdx.x + o];
        }
        __syncthreads();
    }
    if (threadIdx.x == 0) {
        double kd = (double)(Kk * Dd);
        double entropy = (sa[0] / kd);
        double nll = -(sb[0] / kd);
        out[0] = (float)(entropy + nll);
    }
}

extern "C" void kernel_launch(void* const* d_in, const int* in_sizes, int n_in,
                              void* d_out, int out_size) {
    const float* feats = (const float*)d_in[0];
    float* out = (float*)d_out;
    (void)in_sizes; (void)n_in; (void)out_size;

    copy_init_kernel<<<(Kk * Dd + 255) / 256, 256>>>(feats);
    xsq_kernel<<<(Nn * 32) / 256, 256>>>(feats);

    for (int it = 0; it < NUM_ITERS; it++) {
        csq_kernel<<<(Kk * 32) / 256, 256>>>();
        assign_kernel<<<Nn / BM, 128>>>(feats);
        histo_kernel<<<NCHUNK, CHUNK>>>();
        scan_kernel<<<1, Kk>>>();
        scatter_kernel<<<NCHUNK, CHUNK>>>();
        update_kernel<<<Kk, 128>>>(feats);
    }

    csq_kernel<<<(Kk * 32) / 256, 256>>>();
    assign_kernel<<<Nn / BM, 128>>>(feats);
    histo_kernel<<<NCHUNK, CHUNK>>>();
    scan_kernel<<<1, Kk>>>();
    scatter_kernel<<<NCHUNK, CHUNK>>>();
    dists_kernel<<<Kk, 128>>>(feats);

    reduce1_kernel<<<256, 256>>>();
    finalize1_kernel<<<1, 256>>>();
    reduce2_kernel<<<256, 256>>>();
    finalize2_kernel<<<1, 256>>>(out);
}